// round 10
// baseline (speedup 1.0000x reference)
#include <cuda_runtime.h>
#include <cstdint>

#define Bsz 2048
#define Tsz 512
#define Asz 32
#define Hsz 16
#define NCHUNK (Tsz / 8)

typedef unsigned long long u64;
typedef unsigned int u32;

__device__ __forceinline__ void unpack2(u64 v, float& lo, float& hi) {
    asm("mov.b64 {%0, %1}, %2;" : "=f"(lo), "=f"(hi) : "l"(v));
}
__device__ __forceinline__ u64 fma2(u64 a, u64 b, u64 c) {
    u64 d; asm("fma.rn.f32x2 %0, %1, %2, %3;" : "=l"(d) : "l"(a), "l"(b), "l"(c)); return d;
}
__device__ __forceinline__ u64 add2(u64 a, u64 b) {
    u64 d; asm("add.rn.f32x2 %0, %1, %2;" : "=l"(d) : "l"(a), "l"(b)); return d;
}
__device__ __forceinline__ float hsum2(u64 v) {
    float lo, hi; unpack2(v, lo, hi); return lo + hi;
}
__device__ __forceinline__ float tanh_fast(float x) {
    float y; asm("tanh.approx.f32 %0, %1;" : "=f"(y) : "f"(x)); return y;
}
__device__ __forceinline__ float sigmoid_fast(float x) {
    return fmaf(0.5f, tanh_fast(0.5f * x), 0.5f);
}
__device__ __forceinline__ u32 smaddr(const void* p) {
    return (u32)__cvta_generic_to_shared(p);
}
__device__ __forceinline__ void cp16(u32 s, const void* g) {
    asm volatile("cp.async.ca.shared.global [%0], [%1], 16;" :: "r"(s), "l"(g));
}
__device__ __forceinline__ u64 ldg64v(const void* p) {   // un-hoistable LDG
    u64 v; asm volatile("ld.global.nc.b64 %0, [%1];" : "=l"(v) : "l"(p)); return v;
}
__device__ __forceinline__ float ldgf32v(const void* p) {
    float v; asm volatile("ld.global.nc.f32 %0, [%1];" : "=f"(v) : "l"(p)); return v;
}
#define CP_COMMIT() asm volatile("cp.async.commit_group;" ::: "memory")
#define CP_WAIT1()  asm volatile("cp.async.wait_group 1;" ::: "memory")

// ============================================================================
// CTA = 128 threads = 4 warps = 2 batch elements (1 consumer + 1 producer
// warp per element; roles flip with blockIdx parity to mix SMSP load).
//   consumer: recurrence, lo/hi gate split, tanh.approx activations.
//   producer: pregates one chunk AHEAD (cp.async x) + heads one chunk BEHIND
//             (h from 16-deep ring; actor weights reloaded per chunk to keep
//             persistent regs under the 102-reg / 5-CTA cap).
// ============================================================================
__global__ void __launch_bounds__(128, 5) lstm_fused(
    const float* __restrict__ xin, const float* __restrict__ masks,
    const float* __restrict__ h0, const float* __restrict__ c0,
    const float* __restrict__ w_ih, const float* __restrict__ w_hh,
    const float* __restrict__ b_ih, const float* __restrict__ b_hh,
    const float* __restrict__ w_actor, const float* __restrict__ b_actor,
    const float* __restrict__ w_critic, const float* __restrict__ b_critic,
    float* __restrict__ actor, float* __restrict__ critic,
    float* __restrict__ hT, float* __restrict__ cT)
{
    __shared__ __align__(16) float pgsm[2][2][8 * 64];
    __shared__ __align__(16) float xsm[2][2][8 * 32];
    __shared__ __align__(16) float hbuf[2][16][16];     // ring: slot t&15 = h_t
    __shared__ __align__(16) float wc_s[16];

    const int tid  = threadIdx.x;
    const int w    = tid >> 5;
    const int lane = tid & 31;
    const int e    = w & 1;
    const bool is_prod = ((w >> 1) ^ (blockIdx.x & 1)) != 0;
    const int b    = blockIdx.x * 2 + e;

    if (tid < 16) wc_s[tid] = w_critic[tid];

    if (is_prod) {
        // ---------------- PRODUCER ----------------
        u64 wA[16], wB[16];
        {
            const u64* pA = (const u64*)(w_ih + lane * 32);
            const u64* pB = (const u64*)(w_ih + (32 + lane) * 32);
#pragma unroll
            for (int k = 0; k < 16; k++) { wA[k] = pA[k]; wB[k] = pB[k]; }
        }
        const float bsA = b_ih[lane] + b_hh[lane];
        const float bsB = b_ih[32 + lane] + b_hh[32 + lane];

        const float* xb = xin + (size_t)b * Tsz * Asz;
        float* actb     = actor + (size_t)b * Tsz * Asz;
        float* crb      = critic + (size_t)b * Tsz;

        auto loadx = [&](int ch) {
            const int bf = ch & 1;
            u32 dst = smaddr(&xsm[e][bf][0]);
            const float* src = xb + ch * 256;
            cp16(dst + lane * 16,       src + lane * 4);
            cp16(dst + lane * 16 + 512, src + lane * 4 + 128);
        };
        auto comp = [&](int ch) {
            const int bf = ch & 1;
#pragma unroll
            for (int s = 0; s < 8; s++) {
                const ulonglong2* xp = (const ulonglong2*)&xsm[e][bf][s * 32];
                u64 a0 = 0, a1 = 0, g0 = 0, g1 = 0;
#pragma unroll
                for (int q = 0; q < 8; q++) {
                    const ulonglong2 v = xp[q];
                    a0 = fma2(wA[2 * q],     v.x, a0);
                    a1 = fma2(wA[2 * q + 1], v.y, a1);
                    g0 = fma2(wB[2 * q],     v.x, g0);
                    g1 = fma2(wB[2 * q + 1], v.y, g1);
                }
                float2 o;
                o.x = hsum2(add2(a0, a1)) + bsA;
                o.y = hsum2(add2(g0, g1)) + bsB;
                *(float2*)&pgsm[e][bf][s * 64 + 2 * lane] = o;
            }
        };
        auto heads = [&](int cc) {                 // chunk cc: h final in ring
            // reload actor weights each call (volatile: not hoistable -> no
            // persistent registers). 9 L1-hit LDGs per 8 steps.
            u64 wa[8];
            const u64* pa = (const u64*)(w_actor + lane * 16);
#pragma unroll
            for (int k = 0; k < 8; k++) wa[k] = ldg64v(pa + k);
            const float bact = ldgf32v(b_actor + lane);
            const int t0 = cc * 8;
#pragma unroll
            for (int s = 0; s < 8; s++) {
                const int t = t0 + s;
                const ulonglong2* hp = (const ulonglong2*)&hbuf[e][t & 15][0];
                u64 a0 = 0, a1 = 0;
#pragma unroll
                for (int q = 0; q < 4; q++) {
                    const ulonglong2 v = hp[q];
                    a0 = fma2(wa[2 * q],     v.x, a0);
                    a1 = fma2(wa[2 * q + 1], v.y, a1);
                }
                actb[t * Asz + lane] = hsum2(add2(a0, a1)) + bact;
            }
            if (lane < 8) {                        // critic: lane = step
                const float bcr = ldgf32v(b_critic);
                const int t = t0 + lane;
                const u64* hp = (const u64*)&hbuf[e][t & 15][0];
                const u64* wc = (const u64*)wc_s;
                u64 a0 = 0, a1 = 0;
#pragma unroll
                for (int k = 0; k < 4; k++) {
                    a0 = fma2(wc[2 * k],     hp[2 * k],     a0);
                    a1 = fma2(wc[2 * k + 1], hp[2 * k + 1], a1);
                }
                crb[t] = hsum2(add2(a0, a1)) + bcr;
            }
        };

        loadx(0); CP_COMMIT();
        loadx(1); CP_COMMIT();
        CP_WAIT1();
        comp(0);
        __syncthreads();                           // pg chunk 0 ready

        for (int cc = 0; cc < NCHUNK; cc++) {
            if (cc + 2 < NCHUNK) loadx(cc + 2);
            CP_COMMIT();
            CP_WAIT1();
            if (cc + 1 < NCHUNK) comp(cc + 1);
            if (cc >= 1) heads(cc - 1);
            __syncthreads();
        }
        heads(NCHUNK - 1);
    } else {
        // ---------------- CONSUMER (lo/hi gate split, 1 elem) --------------
        const int j = lane & 15;
        const bool hi_half = lane >= 16;

        u64 whP[8], whQ[8];                        // rows lane, 32+lane
        {
            const u64* pP = (const u64*)(w_hh + lane * 16);
            const u64* pQ = (const u64*)(w_hh + (32 + lane) * 16);
#pragma unroll
            for (int k = 0; k < 8; k++) { whP[k] = pP[k]; whQ[k] = pQ[k]; }
        }
        const float* mb = masks + (size_t)b * Tsz;
        float c = c0[b * Hsz + j];
        if (lane < 16) hbuf[e][15][lane] = h0[b * Hsz + lane];  // h_{-1}
        float m_cur = mb[0];
        float h2 = 0.0f;

        __syncthreads();

        for (int cc = 0; cc < NCHUNK; cc++) {
#pragma unroll
            for (int s = 0; s < 8; s++) {
                const int t = cc * 8 + s;
                const float m = m_cur;
                m_cur = mb[(t + 1 < Tsz) ? t + 1 : Tsz - 1];

                u64 hv[8];                          // h_{t-1} broadcast
                {
                    const ulonglong2* hp = (const ulonglong2*)&hbuf[e][(t + 15) & 15][0];
#pragma unroll
                    for (int q = 0; q < 4; q++) {
                        const ulonglong2 v = hp[q];
                        hv[2 * q] = v.x; hv[2 * q + 1] = v.y;
                    }
                }
                u64 aP = 0, aQ = 0;
#pragma unroll
                for (int k = 0; k < 8; k++) {
                    aP = fma2(whP[k], hv[k], aP);
                    aQ = fma2(whQ[k], hv[k], aQ);
                }
                const float sP = hsum2(aP);
                const float sQ = hsum2(aQ);

                const float2 pgv = *(const float2*)&pgsm[e][cc & 1][s * 64 + 2 * lane];

                const float gP = fmaf(m, sP, pgv.x);   // lo: i, hi: f
                const float gQ = fmaf(m, sQ, pgv.y);   // lo: g, hi: o

                const float vP = sigmoid_fast(gP);
                const float tQ = tanh_fast(hi_half ? 0.5f * gQ : gQ);
                const float vQ = hi_half ? fmaf(0.5f, tQ, 0.5f) : tQ;

                const float p  = vP * vQ;                          // lo: i*g
                const float ig = __shfl_sync(0xffffffffu, p, j);   // hi gets i*g

                c  = fmaf(vP, c * m, ig);                          // hi lanes
                h2 = vQ * tanh_fast(c);                            // hi lanes

                if (hi_half) hbuf[e][t & 15][j] = h2;
                __syncwarp();
            }
            __syncthreads();
        }

        if (hi_half) {
            hT[b * Hsz + j] = h2;
            cT[b * Hsz + j] = c;
        }
    }
}

extern "C" void kernel_launch(void* const* d_in, const int* in_sizes, int n_in,
                              void* d_out, int out_size) {
    const float* xin      = (const float*)d_in[0];
    const float* masks    = (const float*)d_in[1];
    const float* h0       = (const float*)d_in[2];
    const float* c0       = (const float*)d_in[3];
    const float* w_ih     = (const float*)d_in[4];
    const float* w_hh     = (const float*)d_in[5];
    const float* b_ih     = (const float*)d_in[6];
    const float* b_hh     = (const float*)d_in[7];
    const float* w_actor  = (const float*)d_in[8];
    const float* b_actor  = (const float*)d_in[9];
    const float* w_critic = (const float*)d_in[10];
    const float* b_critic = (const float*)d_in[11];

    float* out    = (float*)d_out;
    float* actor  = out;
    float* critic = actor + (size_t)Bsz * Tsz * Asz;
    float* hT     = critic + (size_t)Bsz * Tsz;
    float* cT     = hT + (size_t)Bsz * Hsz;

    lstm_fused<<<Bsz / 2, 128>>>(xin, masks, h0, c0, w_ih, w_hh, b_ih, b_hh,
                                 w_actor, b_actor, w_critic, b_critic,
                                 actor, critic, hT, cT);
}

// round 11
// speedup vs baseline: 1.4925x; 1.4925x over previous
#include <cuda_runtime.h>
#include <cstdint>

#define Bsz 2048
#define Tsz 512
#define Asz 32
#define Hsz 16
#define NCHUNK (Tsz / 8)

typedef unsigned long long u64;
typedef unsigned int u32;

__device__ __forceinline__ void unpack2(u64 v, float& lo, float& hi) {
    asm("mov.b64 {%0, %1}, %2;" : "=f"(lo), "=f"(hi) : "l"(v));
}
__device__ __forceinline__ u64 fma2(u64 a, u64 b, u64 c) {
    u64 d; asm("fma.rn.f32x2 %0, %1, %2, %3;" : "=l"(d) : "l"(a), "l"(b), "l"(c)); return d;
}
__device__ __forceinline__ u64 add2(u64 a, u64 b) {
    u64 d; asm("add.rn.f32x2 %0, %1, %2;" : "=l"(d) : "l"(a), "l"(b)); return d;
}
__device__ __forceinline__ float hsum2(u64 v) {
    float lo, hi; unpack2(v, lo, hi); return lo + hi;
}
__device__ __forceinline__ float tanh_fast(float x) {
    float y; asm("tanh.approx.f32 %0, %1;" : "=f"(y) : "f"(x)); return y;
}
__device__ __forceinline__ float sigmoid_fast(float x) {
    return fmaf(0.5f, tanh_fast(0.5f * x), 0.5f);
}
__device__ __forceinline__ u32 smaddr(const void* p) {
    return (u32)__cvta_generic_to_shared(p);
}
__device__ __forceinline__ void cp16(u32 s, const void* g) {
    asm volatile("cp.async.ca.shared.global [%0], [%1], 16;" :: "r"(s), "l"(g));
}
#define CP_COMMIT() asm volatile("cp.async.commit_group;" ::: "memory")
#define CP_WAIT1()  asm volatile("cp.async.wait_group 1;" ::: "memory")

// ============================================================================
// CTA = 128 threads = 4 warps = 2 batch elements.
//   consumer warp (1 elem): recurrence, lo/hi gate split (lane j: i_j,g_j;
//     lane 16+j: f_j,o_j), tanh.approx activations (rel_err ~6e-6, validated).
//   producer warp (1 elem): pregates one chunk AHEAD (cp.async x double
//     buffer) + actor/critic heads one chunk BEHIND (h from 16-deep ring).
//     Actor weights stay in registers (R10's reload hack regressed).
// Roles flip with blockIdx parity so SMSPs get a mixed load.
// One __syncthreads per chunk; pg never touches HBM.
// ============================================================================
__global__ void __launch_bounds__(128, 4) lstm_fused(
    const float* __restrict__ xin, const float* __restrict__ masks,
    const float* __restrict__ h0, const float* __restrict__ c0,
    const float* __restrict__ w_ih, const float* __restrict__ w_hh,
    const float* __restrict__ b_ih, const float* __restrict__ b_hh,
    const float* __restrict__ w_actor, const float* __restrict__ b_actor,
    const float* __restrict__ w_critic, const float* __restrict__ b_critic,
    float* __restrict__ actor, float* __restrict__ critic,
    float* __restrict__ hT, float* __restrict__ cT)
{
    __shared__ __align__(16) float pgsm[2][2][8 * 64];  // 8KB
    __shared__ __align__(16) float xsm[2][2][8 * 32];   // 4KB
    __shared__ __align__(16) float hbuf[2][16][16];     // 2KB ring: slot t&15 = h_t
    __shared__ __align__(16) float wc_s[16];

    const int tid  = threadIdx.x;
    const int w    = tid >> 5;
    const int lane = tid & 31;
    const int e    = w & 1;                       // element within CTA
    const bool is_prod = ((w >> 1) ^ (blockIdx.x & 1)) != 0;
    const int b    = blockIdx.x * 2 + e;

    if (tid < 16) wc_s[tid] = w_critic[tid];

    if (is_prod) {
        // ---------------- PRODUCER ----------------
        u64 wA[16], wB[16];
        {
            const u64* pA = (const u64*)(w_ih + lane * 32);
            const u64* pB = (const u64*)(w_ih + (32 + lane) * 32);
#pragma unroll
            for (int k = 0; k < 16; k++) { wA[k] = pA[k]; wB[k] = pB[k]; }
        }
        const float bsA = b_ih[lane] + b_hh[lane];
        const float bsB = b_ih[32 + lane] + b_hh[32 + lane];
        u64 wa[8];                                 // actor row = lane
        {
            const u64* pa = (const u64*)(w_actor + lane * 16);
#pragma unroll
            for (int k = 0; k < 8; k++) wa[k] = pa[k];
        }
        const float bact = b_actor[lane];
        const float bcr  = b_critic[0];

        const float* xb = xin + (size_t)b * Tsz * Asz;
        float* actb     = actor + (size_t)b * Tsz * Asz;
        float* crb      = critic + (size_t)b * Tsz;

        auto loadx = [&](int ch) {
            const int bf = ch & 1;
            u32 dst = smaddr(&xsm[e][bf][0]);
            const float* src = xb + ch * 256;
            cp16(dst + lane * 16,       src + lane * 4);
            cp16(dst + lane * 16 + 512, src + lane * 4 + 128);
        };
        auto comp = [&](int ch) {
            const int bf = ch & 1;
#pragma unroll
            for (int s = 0; s < 8; s++) {
                const ulonglong2* xp = (const ulonglong2*)&xsm[e][bf][s * 32];
                u64 a0 = 0, a1 = 0, g0 = 0, g1 = 0;
#pragma unroll
                for (int q = 0; q < 8; q++) {
                    const ulonglong2 v = xp[q];
                    a0 = fma2(wA[2 * q],     v.x, a0);
                    a1 = fma2(wA[2 * q + 1], v.y, a1);
                    g0 = fma2(wB[2 * q],     v.x, g0);
                    g1 = fma2(wB[2 * q + 1], v.y, g1);
                }
                float2 o;
                o.x = hsum2(add2(a0, a1)) + bsA;
                o.y = hsum2(add2(g0, g1)) + bsB;
                *(float2*)&pgsm[e][bf][s * 64 + 2 * lane] = o;
            }
        };
        auto heads = [&](int cc) {                 // chunk cc (h final in ring)
            const int t0 = cc * 8;
#pragma unroll
            for (int s = 0; s < 8; s++) {
                const int t = t0 + s;
                const ulonglong2* hp = (const ulonglong2*)&hbuf[e][t & 15][0];
                u64 a0 = 0, a1 = 0;
#pragma unroll
                for (int q = 0; q < 4; q++) {
                    const ulonglong2 v = hp[q];
                    a0 = fma2(wa[2 * q],     v.x, a0);
                    a1 = fma2(wa[2 * q + 1], v.y, a1);
                }
                actb[t * Asz + lane] = hsum2(add2(a0, a1)) + bact;
            }
            if (lane < 8) {                        // critic: lane = step
                const int t = t0 + lane;
                const u64* hp = (const u64*)&hbuf[e][t & 15][0];
                const u64* wc = (const u64*)wc_s;  // broadcast smem
                u64 a0 = 0, a1 = 0;
#pragma unroll
                for (int k = 0; k < 4; k++) {
                    a0 = fma2(wc[2 * k],     hp[2 * k],     a0);
                    a1 = fma2(wc[2 * k + 1], hp[2 * k + 1], a1);
                }
                crb[t] = hsum2(add2(a0, a1)) + bcr;
            }
        };

        loadx(0); CP_COMMIT();
        loadx(1); CP_COMMIT();
        CP_WAIT1();
        comp(0);
        __syncthreads();                           // pg chunk 0 ready

        for (int cc = 0; cc < NCHUNK; cc++) {
            if (cc + 2 < NCHUNK) loadx(cc + 2);
            CP_COMMIT();
            CP_WAIT1();                            // x_{cc+1} landed
            if (cc + 1 < NCHUNK) comp(cc + 1);
            if (cc >= 1) heads(cc - 1);            // h chunk cc-1 final
            __syncthreads();
        }
        heads(NCHUNK - 1);
    } else {
        // ---------------- CONSUMER (lo/hi gate split, 1 elem) --------------
        const int j = lane & 15;
        const bool hi_half = lane >= 16;

        u64 whP[8], whQ[8];                        // rows lane, 32+lane
        {
            const u64* pP = (const u64*)(w_hh + lane * 16);
            const u64* pQ = (const u64*)(w_hh + (32 + lane) * 16);
#pragma unroll
            for (int k = 0; k < 8; k++) { whP[k] = pP[k]; whQ[k] = pQ[k]; }
        }
        const float* mb = masks + (size_t)b * Tsz;
        float c = c0[b * Hsz + j];
        if (lane < 16) hbuf[e][15][lane] = h0[b * Hsz + lane];  // h_{-1}
        float m_cur = mb[0];
        float h2 = 0.0f;

        __syncthreads();                           // match producer prologue

        for (int cc = 0; cc < NCHUNK; cc++) {
#pragma unroll
            for (int s = 0; s < 8; s++) {
                const int t = cc * 8 + s;
                const float m = m_cur;
                m_cur = mb[(t + 1 < Tsz) ? t + 1 : Tsz - 1];
                const float cm = c * m;             // off-chain early

                u64 hv[8];                          // h_{t-1} broadcast
                {
                    const ulonglong2* hp = (const ulonglong2*)&hbuf[e][(t + 15) & 15][0];
#pragma unroll
                    for (int q = 0; q < 4; q++) {
                        const ulonglong2 v = hp[q];
                        hv[2 * q] = v.x; hv[2 * q + 1] = v.y;
                    }
                }
                u64 aP = 0, aQ = 0;
#pragma unroll
                for (int k = 0; k < 8; k++) {
                    aP = fma2(whP[k], hv[k], aP);
                    aQ = fma2(whQ[k], hv[k], aQ);
                }
                const float sP = hsum2(aP);
                const float sQ = hsum2(aQ);

                const float2 pgv = *(const float2*)&pgsm[e][cc & 1][s * 64 + 2 * lane];

                const float gP = fmaf(m, sP, pgv.x);   // lo: i, hi: f
                const float gQ = fmaf(m, sQ, pgv.y);   // lo: g, hi: o

                const float vP = sigmoid_fast(gP);
                const float tQ = tanh_fast(hi_half ? 0.5f * gQ : gQ);
                const float vQ = hi_half ? fmaf(0.5f, tQ, 0.5f) : tQ;  // o / tanh(g)

                const float p  = vP * vQ;                          // lo: i*g
                const float ig = __shfl_sync(0xffffffffu, p, j);   // hi gets i*g

                c  = fmaf(vP, cm, ig);                             // hi: f*(c*m)+i*g
                h2 = vQ * tanh_fast(c);                            // hi: o*tanh(c)

                if (hi_half) hbuf[e][t & 15][j] = h2;
                __syncwarp();
            }
            __syncthreads();
        }

        if (hi_half) {
            hT[b * Hsz + j] = h2;
            cT[b * Hsz + j] = c;
        }
    }
}

extern "C" void kernel_launch(void* const* d_in, const int* in_sizes, int n_in,
                              void* d_out, int out_size) {
    const float* xin      = (const float*)d_in[0];
    const float* masks    = (const float*)d_in[1];
    const float* h0       = (const float*)d_in[2];
    const float* c0       = (const float*)d_in[3];
    const float* w_ih     = (const float*)d_in[4];
    const float* w_hh     = (const float*)d_in[5];
    const float* b_ih     = (const float*)d_in[6];
    const float* b_hh     = (const float*)d_in[7];
    const float* w_actor  = (const float*)d_in[8];
    const float* b_actor  = (const float*)d_in[9];
    const float* w_critic = (const float*)d_in[10];
    const float* b_critic = (const float*)d_in[11];

    float* out    = (float*)d_out;
    float* actor  = out;
    float* critic = actor + (size_t)Bsz * Tsz * Asz;
    float* hT     = critic + (size_t)Bsz * Tsz;
    float* cT     = hT + (size_t)Bsz * Hsz;

    lstm_fused<<<Bsz / 2, 128>>>(xin, masks, h0, c0, w_ih, w_hh, b_ih, b_hh,
                                 w_actor, b_actor, w_critic, b_critic,
                                 actor, critic, hT, cT);
}